// round 15
// baseline (speedup 1.0000x reference)
#include <cuda_runtime.h>
#include <cuda_bf16.h>
#include <cstdint>

#define NNODE 50000
#define NEDGE 800000
#define HD 128
#define NLAYER 4
#define TE 64           // edges/nodes per block tile

__device__ float g_h[NNODE * HD];
__device__ float g_agg[NNODE * HD];
__device__ float g_P[NNODE * HD];
__device__ float g_Q[NNODE * HD];
__device__ float g_d2[NEDGE];
// fragment-major split-bf16 weight images:
// entry r=(ks*S+s)*32+lane -> uint4(B0hi,B0lo,B1hi,B1lo), col n=8s+(lane>>2),
// kpairs kp0=8ks+(lane&3), kp1=kp0+4 (S = N/8 s-values per ks).
__device__ uint4 g_w2te[NLAYER][4096];    // edge W2,  K=128, N=128
__device__ uint4 g_nw1te[NLAYER][8192];   // node W1,  K=256, N=128
__device__ uint4 g_nw2te[NLAYER][4096];   // node W2,  K=128, N=128
__device__ uint4 g_w1te[NLAYER][8192];    // edge W1 P||Q, K=128, N=256

__device__ __forceinline__ float silu(float x) {
    return x / (1.0f + __expf(-x));
}
__device__ __forceinline__ uint32_t packbf(float lo_e, float hi_e) {
    return ((uint32_t)__bfloat16_as_ushort(__float2bfloat16_rn(hi_e)) << 16)
         |  (uint32_t)__bfloat16_as_ushort(__float2bfloat16_rn(lo_e));
}
__device__ __forceinline__ void splitbf(float2 v, uint32_t& hiw, uint32_t& low) {
    __nv_bfloat16 h0 = __float2bfloat16_rn(v.x);
    __nv_bfloat16 h1 = __float2bfloat16_rn(v.y);
    hiw = ((uint32_t)__bfloat16_as_ushort(h1) << 16)
        |  (uint32_t)__bfloat16_as_ushort(h0);
    low = packbf(v.x - __bfloat162float(h0), v.y - __bfloat162float(h1));
}

// m16n8k16 bf16 mma, fp32 accumulate (sm_80+ PTX)
#define MMA_BF16(c, a0, a1, a2, a3, b0, b1) \
    asm volatile("mma.sync.aligned.m16n8k16.row.col.f32.bf16.bf16.f32 " \
        "{%0,%1,%2,%3}, {%4,%5,%6,%7}, {%8,%9}, {%0,%1,%2,%3};" \
        : "+f"((c)[0]), "+f"((c)[1]), "+f"((c)[2]), "+f"((c)[3]) \
        : "r"(a0), "r"(a1), "r"(a2), "r"(a3), "r"(b0), "r"(b1))

// coalesced vector reduction (sm_90+)
#define REDV4(addr, v) \
    asm volatile("red.global.add.v4.f32 [%0], {%1,%2,%3,%4};" \
        :: "l"(addr), "f"((v).x), "f"((v).y), "f"((v).z), "f"((v).w) : "memory")

__global__ void k_init(const int* __restrict__ z, const float* __restrict__ emb) {
    int i = blockIdx.x * 256 + threadIdx.x;
    if (i < NNODE * HD) {
        g_h[i] = emb[(z[i >> 7] << 7) | (i & 127)];
        g_agg[i] = 0.0f;
    }
}

__global__ void k_d2(const float* __restrict__ pos, const int* __restrict__ ei) {
    int e = blockIdx.x * 256 + threadIdx.x;
    if (e < NEDGE) {
        int r = ei[e], c = ei[NEDGE + e];
        float dx = pos[3 * r + 0] - pos[3 * c + 0];
        float dy = pos[3 * r + 1] - pos[3 * c + 1];
        float dz = pos[3 * r + 2] - pos[3 * c + 2];
        g_d2[e] = dx * dx + dy * dy + dz * dz;
    }
}

// Fragment-major split-bf16 weight image builder (N=128 images).
__global__ void k_prepw(const float* __restrict__ src, int ksteps,
                        int layer_stride, int which) {
    int per = ksteps * 512;
    int idx = blockIdx.x * 256 + threadIdx.x;
    if (idx >= NLAYER * per) return;
    int l = idx / per, r = idx % per;
    int ks = r >> 9, s = (r >> 5) & 15, lane = r & 31;
    int g = lane >> 2, t = lane & 3;
    int n = 8 * s + g;
    int kp0 = 8 * ks + t, kp1 = kp0 + 4;
    const float* W = src + (size_t)l * layer_stride;

    uint4 v;
    splitbf(make_float2(W[(size_t)(2 * kp0) * HD + n],
                        W[(size_t)(2 * kp0 + 1) * HD + n]), v.x, v.y);
    splitbf(make_float2(W[(size_t)(2 * kp1) * HD + n],
                        W[(size_t)(2 * kp1 + 1) * HD + n]), v.z, v.w);
    if (which == 0)      g_w2te[l][r] = v;
    else if (which == 1) g_nw1te[l][r] = v;
    else                 g_nw2te[l][r] = v;
}

// Fragment-major image for edge W1 as fused P||Q GEMM (K=128, N=256).
__global__ void k_prepw1(const float* __restrict__ ew1) {
    int idx = blockIdx.x * 256 + threadIdx.x;     // NLAYER * 8192
    if (idx >= NLAYER * 8192) return;
    int l = idx >> 13, r = idx & 8191;
    int ks = r >> 10, s = (r >> 5) & 31, lane = r & 31;
    int g = lane >> 2, t = lane & 3;
    int n = 8 * s + g;                 // 0..255
    int j = n & 127;
    int koff = (n >= 128) ? 128 : 0;
    int kp0 = 8 * ks + t, kp1 = kp0 + 4;
    const float* W = ew1 + (size_t)l * 257 * HD;

    uint4 v;
    splitbf(make_float2(W[(size_t)(2 * kp0 + koff) * HD + j],
                        W[(size_t)(2 * kp0 + 1 + koff) * HD + j]), v.x, v.y);
    splitbf(make_float2(W[(size_t)(2 * kp1 + koff) * HD + j],
                        W[(size_t)(2 * kp1 + 1 + koff) * HD + j]), v.z, v.w);
    g_w1te[l][r] = v;
}

// P||Q = h @ [W1_top || W1_bot] on tensor cores (Round-14, proven).
__global__ __launch_bounds__(512) void k_pq(int layer) {
    __shared__ uint32_t xhi[TE][68];
    __shared__ uint32_t xlo[TE][68];

    const int tid = threadIdx.x;
    const int warp = tid >> 5, lane = tid & 31;
    const int nb0 = blockIdx.x * TE;

    for (int r = warp; r < TE; r += 16) {
        int node = nb0 + r;
        if (node >= NNODE) node = 0;
        const float* hp = g_h + (size_t)node * HD;
        #pragma unroll
        for (int s = 0; s < 2; s++) {
            int kp = lane + 32 * s;
            float2 hv = __ldg((const float2*)(hp + 2 * kp));
            splitbf(hv, xhi[r][kp], xlo[r][kp]);
        }
    }
    __syncthreads();

    const int g = lane >> 2, t = lane & 3;
    const int m0 = 16 * (warp & 3);
    const int sbase = (warp >> 2) * 8;
    const int n0 = 8 * sbase;
    const int r0 = m0 + g, r1 = m0 + 8 + g;

    float c[8][4];
    #pragma unroll
    for (int s = 0; s < 8; s++)
        #pragma unroll
        for (int q = 0; q < 4; q++) c[s][q] = 0.0f;

    const uint4* bw = &g_w1te[layer][0];

    #pragma unroll
    for (int ks = 0; ks < 8; ks++) {
        uint32_t a0h = xhi[r0][8 * ks + t];
        uint32_t a1h = xhi[r1][8 * ks + t];
        uint32_t a2h = xhi[r0][8 * ks + 4 + t];
        uint32_t a3h = xhi[r1][8 * ks + 4 + t];
        uint32_t a0l = xlo[r0][8 * ks + t];
        uint32_t a1l = xlo[r1][8 * ks + t];
        uint32_t a2l = xlo[r0][8 * ks + 4 + t];
        uint32_t a3l = xlo[r1][8 * ks + 4 + t];
        #pragma unroll
        for (int s = 0; s < 8; s++) {
            uint4 B = __ldg(bw + ((ks * 32 + sbase + s) * 32 + lane));
            MMA_BF16(c[s], a0h, a1h, a2h, a3h, B.x, B.z);
            MMA_BF16(c[s], a0l, a1l, a2l, a3l, B.x, B.z);
            MMA_BF16(c[s], a0h, a1h, a2h, a3h, B.y, B.w);
        }
    }

    {
        int nd0 = nb0 + r0, nd1 = nb0 + r1;
        #pragma unroll
        for (int s = 0; s < 8; s++) {
            int col = n0 + 8 * s + 2 * t;
            float* base = (col < 128) ? g_P : g_Q;
            int cc = col & 127;
            if (nd0 < NNODE)
                *(float2*)(base + (size_t)nd0 * HD + cc) = make_float2(c[s][0], c[s][1]);
            if (nd1 < NNODE)
                *(float2*)(base + (size_t)nd1 * HD + cc) = make_float2(c[s][2], c[s][3]);
        }
    }
}

// Edge kernel: tensor-core GEMM2; epilogue transposed via smem overlay,
// aggregation via coalesced red.global.add.v4.f32.
__global__ __launch_bounds__(256) void k_edge(
    const int* __restrict__ ei,
    const float* __restrict__ W1,            // row 256 = d2 weights
    const float* __restrict__ b1,
    const float* __restrict__ b2, int layer)
{
    __shared__ __align__(16) unsigned char sbuf[TE * 68 * 4 * 2];  // 34816 B
    __shared__ int srow[TE], scols[TE];
    __shared__ float sd2[TE], s_b1[HD], s_wl[HD], s_b2[HD];

    uint32_t (*xhi)[68] = (uint32_t(*)[68])sbuf;
    uint32_t (*xlo)[68] = (uint32_t(*)[68])(sbuf + TE * 68 * 4);
    float (*ys)[132]    = (float(*)[132])sbuf;   // overlay after MMA (33792 B)

    const int tid = threadIdx.x;
    const int warp = tid >> 5, lane = tid & 31;
    const int e0 = blockIdx.x * TE;

    if (tid < TE) { srow[tid] = ei[e0 + tid]; sd2[tid] = g_d2[e0 + tid]; }
    else if (tid < 2 * TE) scols[tid - TE] = ei[NEDGE + e0 + (tid - TE)];
    if (tid < HD) {
        s_b1[tid] = __ldg(b1 + tid);
        s_wl[tid] = __ldg(W1 + 256 * HD + tid);
        s_b2[tid] = __ldg(b2 + tid);
    }
    __syncthreads();

    for (int e = warp; e < TE; e += 8) {
        const float* pp = g_P + (size_t)srow[e] * HD;
        const float* qq = g_Q + (size_t)scols[e] * HD;
        float d2e = sd2[e];
        #pragma unroll
        for (int s = 0; s < 2; s++) {
            int kp = lane + 32 * s;
            float2 pv = __ldg((const float2*)(pp + 2 * kp));
            float2 qv = __ldg((const float2*)(qq + 2 * kp));
            float u0 = silu(pv.x + qv.x + d2e * s_wl[2 * kp]     + s_b1[2 * kp]);
            float u1 = silu(pv.y + qv.y + d2e * s_wl[2 * kp + 1] + s_b1[2 * kp + 1]);
            splitbf(make_float2(u0, u1), xhi[e][kp], xlo[e][kp]);
        }
    }
    __syncthreads();

    const int g = lane >> 2, t = lane & 3;
    const int m0 = 16 * (warp & 3);
    const int sbase = (warp >> 2) * 8;
    const int n0 = 8 * sbase;
    const int r0 = m0 + g, r1 = m0 + 8 + g;

    float c[8][4];
    #pragma unroll
    for (int s = 0; s < 8; s++)
        #pragma unroll
        for (int q = 0; q < 4; q++) c[s][q] = 0.0f;

    const uint4* bw = &g_w2te[layer][0];

    #pragma unroll
    for (int ks = 0; ks < 8; ks++) {
        uint32_t a0h = xhi[r0][8 * ks + t];
        uint32_t a1h = xhi[r1][8 * ks + t];
        uint32_t a2h = xhi[r0][8 * ks + 4 + t];
        uint32_t a3h = xhi[r1][8 * ks + 4 + t];
        uint32_t a0l = xlo[r0][8 * ks + t];
        uint32_t a1l = xlo[r1][8 * ks + t];
        uint32_t a2l = xlo[r0][8 * ks + 4 + t];
        uint32_t a3l = xlo[r1][8 * ks + 4 + t];
        #pragma unroll
        for (int s = 0; s < 8; s++) {
            uint4 B = __ldg(bw + ((ks * 16 + sbase + s) * 32 + lane));
            MMA_BF16(c[s], a0h, a1h, a2h, a3h, B.x, B.z);
            MMA_BF16(c[s], a0l, a1l, a2l, a3l, B.x, B.z);
            MMA_BF16(c[s], a0h, a1h, a2h, a3h, B.y, B.w);
        }
    }
    __syncthreads();   // all xhi/xlo reads done; ys overlays sbuf

    // transposed epilogue: ys[edge][col] = silu(D + b2)
    #pragma unroll
    for (int s = 0; s < 8; s++) {
        int col = n0 + 8 * s + 2 * t;
        float bb0 = s_b2[col], bb1 = s_b2[col + 1];
        *(float2*)&ys[r0][col] = make_float2(silu(c[s][0] + bb0), silu(c[s][1] + bb1));
        *(float2*)&ys[r1][col] = make_float2(silu(c[s][2] + bb0), silu(c[s][3] + bb1));
    }
    __syncthreads();

    // coalesced vector reduction: one 512B burst per edge row
    for (int e = warp; e < TE; e += 8) {
        float4 v = *(const float4*)&ys[e][4 * lane];
        REDV4(g_agg + (size_t)srow[e] * HD + 4 * lane, v);
    }
}

// Node MLP + residual + LayerNorm on tensor cores (Round-13, proven).
__global__ __launch_bounds__(256) void k_node(
    const float* __restrict__ b1, const float* __restrict__ b2,
    const float* __restrict__ lng, const float* __restrict__ lnb,
    float* __restrict__ out, int use_out, int layer)
{
    __shared__ __align__(16) unsigned char sbuf0[64 * 132 * 4];
    __shared__ __align__(16) unsigned char sbuf1[64 * 132 * 4];
    __shared__ float s_b1[HD], s_b2[HD], s_g[HD], s_bb[HD];

    uint32_t (*xhi)[132] = (uint32_t(*)[132])sbuf0;
    uint32_t (*xlo)[132] = (uint32_t(*)[132])sbuf1;
    uint32_t (*thi)[68]  = (uint32_t(*)[68])sbuf0;
    uint32_t (*tlo)[68]  = (uint32_t(*)[68])sbuf1;
    float (*ys)[132]     = (float(*)[132])sbuf0;

    const int tid = threadIdx.x;
    const int warp = tid >> 5, lane = tid & 31;
    const int nb0 = blockIdx.x * TE;

    if (tid < HD) {
        s_b1[tid] = __ldg(b1 + tid);
        s_b2[tid] = __ldg(b2 + tid);
        s_g[tid]  = __ldg(lng + tid);
        s_bb[tid] = __ldg(lnb + tid);
    }

    for (int r = warp; r < TE; r += 8) {
        int node = nb0 + r;
        int valid = node < NNODE;
        if (!valid) node = 0;
        const float* hp = g_h + (size_t)node * HD;
        float* ap = g_agg + (size_t)node * HD;
        #pragma unroll
        for (int s = 0; s < 2; s++) {
            int kp = lane + 32 * s;
            float2 hv = __ldg((const float2*)(hp + 2 * kp));
            splitbf(hv, xhi[r][kp], xlo[r][kp]);
            float2 av = *(const float2*)(ap + 2 * kp);
            splitbf(av, xhi[r][64 + kp], xlo[r][64 + kp]);
            if (valid) *(float2*)(ap + 2 * kp) = make_float2(0.f, 0.f);
        }
    }
    __syncthreads();

    const int g = lane >> 2, t = lane & 3;
    const int m0 = 16 * (warp & 3);
    const int sbase = (warp >> 2) * 8;
    const int n0 = 8 * sbase;
    const int r0 = m0 + g, r1 = m0 + 8 + g;

    float c[8][4];
    #pragma unroll
    for (int s = 0; s < 8; s++)
        #pragma unroll
        for (int q = 0; q < 4; q++) c[s][q] = 0.0f;

    {
        const uint4* bw = &g_nw1te[layer][0];
        #pragma unroll
        for (int ks = 0; ks < 16; ks++) {
            uint32_t a0h = xhi[r0][8 * ks + t];
            uint32_t a1h = xhi[r1][8 * ks + t];
            uint32_t a2h = xhi[r0][8 * ks + 4 + t];
            uint32_t a3h = xhi[r1][8 * ks + 4 + t];
            uint32_t a0l = xlo[r0][8 * ks + t];
            uint32_t a1l = xlo[r1][8 * ks + t];
            uint32_t a2l = xlo[r0][8 * ks + 4 + t];
            uint32_t a3l = xlo[r1][8 * ks + 4 + t];
            #pragma unroll
            for (int s = 0; s < 8; s++) {
                uint4 B = __ldg(bw + ((ks * 16 + sbase + s) * 32 + lane));
                MMA_BF16(c[s], a0h, a1h, a2h, a3h, B.x, B.z);
                MMA_BF16(c[s], a0l, a1l, a2l, a3l, B.x, B.z);
                MMA_BF16(c[s], a0h, a1h, a2h, a3h, B.y, B.w);
            }
        }
    }
    __syncthreads();

    #pragma unroll
    for (int s = 0; s < 8; s++) {
        int col = n0 + 8 * s + 2 * t;
        int kt = (col >> 1);
        float u0 = silu(c[s][0] + s_b1[col]);
        float u1 = silu(c[s][1] + s_b1[col + 1]);
        float u2 = silu(c[s][2] + s_b1[col]);
        float u3 = silu(c[s][3] + s_b1[col + 1]);
        splitbf(make_float2(u0, u1), thi[r0][kt], tlo[r0][kt]);
        splitbf(make_float2(u2, u3), thi[r1][kt], tlo[r1][kt]);
    }
    __syncthreads();

    #pragma unroll
    for (int s = 0; s < 8; s++)
        #pragma unroll
        for (int q = 0; q < 4; q++) c[s][q] = 0.0f;
    {
        const uint4* bw = &g_nw2te[layer][0];
        #pragma unroll
        for (int ks = 0; ks < 8; ks++) {
            uint32_t a0h = thi[r0][8 * ks + t];
            uint32_t a1h = thi[r1][8 * ks + t];
            uint32_t a2h = thi[r0][8 * ks + 4 + t];
            uint32_t a3h = thi[r1][8 * ks + 4 + t];
            uint32_t a0l = tlo[r0][8 * ks + t];
            uint32_t a1l = tlo[r1][8 * ks + t];
            uint32_t a2l = tlo[r0][8 * ks + 4 + t];
            uint32_t a3l = tlo[r1][8 * ks + 4 + t];
            #pragma unroll
            for (int s = 0; s < 8; s++) {
                uint4 B = __ldg(bw + ((ks * 16 + sbase + s) * 32 + lane));
                MMA_BF16(c[s], a0h, a1h, a2h, a3h, B.x, B.z);
                MMA_BF16(c[s], a0l, a1l, a2l, a3l, B.x, B.z);
                MMA_BF16(c[s], a0h, a1h, a2h, a3h, B.y, B.w);
            }
        }
    }
    __syncthreads();

    {
        int nd0 = nb0 + r0; if (nd0 >= NNODE) nd0 = 0;
        int nd1 = nb0 + r1; if (nd1 >= NNODE) nd1 = 0;
        const float* hp0 = g_h + (size_t)nd0 * HD;
        const float* hp1 = g_h + (size_t)nd1 * HD;
        #pragma unroll
        for (int s = 0; s < 8; s++) {
            int col = n0 + 8 * s + 2 * t;
            float2 h0 = __ldg((const float2*)(hp0 + col));
            float2 h1 = __ldg((const float2*)(hp1 + col));
            ys[r0][col]     = c[s][0] + s_b2[col]     + h0.x;
            ys[r0][col + 1] = c[s][1] + s_b2[col + 1] + h0.y;
            ys[r1][col]     = c[s][2] + s_b2[col]     + h1.x;
            ys[r1][col + 1] = c[s][3] + s_b2[col + 1] + h1.y;
        }
    }
    __syncthreads();

    float* hout = use_out ? out : g_h;
    #pragma unroll
    for (int tt = 0; tt < 8; tt++) {
        int e = warp * 8 + tt;
        int node = nb0 + e;
        float v0 = ys[e][lane +  0];
        float v1 = ys[e][lane + 32];
        float v2 = ys[e][lane + 64];
        float v3 = ys[e][lane + 96];
        float s  = v0 + v1 + v2 + v3;
        float ss = fmaf(v0, v0, fmaf(v1, v1, fmaf(v2, v2, v3 * v3)));
        #pragma unroll
        for (int o = 16; o; o >>= 1) {
            s  += __shfl_xor_sync(0xffffffffu, s, o);
            ss += __shfl_xor_sync(0xffffffffu, ss, o);
        }
        float mu  = s * (1.0f / 128.0f);
        float inv = rsqrtf(ss * (1.0f / 128.0f) - mu * mu + 1e-5f);
        if (node < NNODE) {
            float* dst = hout + (size_t)node * HD;
            dst[lane +  0] = fmaf(s_g[lane +  0], (v0 - mu) * inv, s_bb[lane +  0]);
            dst[lane + 32] = fmaf(s_g[lane + 32], (v1 - mu) * inv, s_bb[lane + 32]);
            dst[lane + 64] = fmaf(s_g[lane + 64], (v2 - mu) * inv, s_bb[lane + 64]);
            dst[lane + 96] = fmaf(s_g[lane + 96], (v3 - mu) * inv, s_bb[lane + 96]);
        }
    }
}

extern "C" void kernel_launch(void* const* d_in, const int* in_sizes, int n_in,
                              void* d_out, int out_size) {
    const int*   z   = (const int*)d_in[0];
    const float* pos = (const float*)d_in[1];
    const int*   ei  = (const int*)d_in[2];
    const float* emb = (const float*)d_in[3];
    const float* ew1 = (const float*)d_in[4];
    const float* eb1 = (const float*)d_in[5];
    const float* ew2 = (const float*)d_in[6];
    const float* eb2 = (const float*)d_in[7];
    const float* nw1 = (const float*)d_in[8];
    const float* nb1 = (const float*)d_in[9];
    const float* nw2 = (const float*)d_in[10];
    const float* nb2 = (const float*)d_in[11];
    const float* lng = (const float*)d_in[12];
    const float* lnb = (const float*)d_in[13];
    float* out = (float*)d_out;

    k_init<<<(NNODE * HD + 255) / 256, 256>>>(z, emb);
    k_d2<<<(NEDGE + 255) / 256, 256>>>(pos, ei);
    k_prepw<<<(NLAYER * 4096 + 255) / 256, 256>>>(ew2, 8, HD * HD, 0);
    k_prepw<<<(NLAYER * 8192 + 255) / 256, 256>>>(nw1, 16, 2 * HD * HD, 1);
    k_prepw<<<(NLAYER * 4096 + 255) / 256, 256>>>(nw2, 8, HD * HD, 2);
    k_prepw1<<<(NLAYER * 8192 + 255) / 256, 256>>>(ew1);

    const int pqgrid = (NNODE + TE - 1) / TE;   // 782
    const int egrid  = NEDGE / TE;              // 12500
    const int ngrid  = (NNODE + TE - 1) / TE;   // 782

    for (int l = 0; l < NLAYER; l++) {
        const float* W1l = ew1 + (size_t)l * 257 * HD;
        k_pq<<<pqgrid, 512>>>(l);
        k_edge<<<egrid, 256>>>(ei, W1l, eb1 + l * HD, eb2 + l * HD, l);
        k_node<<<ngrid, 256>>>(nb1 + l * HD, nb2 + l * HD,
                               lng + l * HD, lnb + l * HD,
                               out, (l == NLAYER - 1) ? 1 : 0, l);
    }
}

// round 16
// speedup vs baseline: 1.0839x; 1.0839x over previous
#include <cuda_runtime.h>
#include <cuda_bf16.h>
#include <cstdint>

#define NNODE 50000
#define NEDGE 800000
#define HD 128
#define NLAYER 4
#define TE 64           // edges/nodes per block tile

__device__ float g_h[NNODE * HD];
__device__ float g_agg[NNODE * HD];
__device__ float g_P[NNODE * HD];
__device__ float g_Q[NNODE * HD];
__device__ float g_d2[NEDGE];
// fragment-major split-bf16 weight images:
// entry r=(ks*S+s)*32+lane -> uint4(B0hi,B0lo,B1hi,B1lo), col n=8s+(lane>>2),
// kpairs kp0=8ks+(lane&3), kp1=kp0+4 (S = N/8 s-values per ks).
__device__ uint4 g_w2te[NLAYER][4096];    // edge W2,  K=128, N=128
__device__ uint4 g_nw1te[NLAYER][8192];   // node W1,  K=256, N=128
__device__ uint4 g_nw2te[NLAYER][4096];   // node W2,  K=128, N=128
__device__ uint4 g_w1te[NLAYER][8192];    // edge W1 P||Q, K=128, N=256

__device__ __forceinline__ float silu(float x) {
    return x / (1.0f + __expf(-x));
}
__device__ __forceinline__ uint32_t packbf(float lo_e, float hi_e) {
    return ((uint32_t)__bfloat16_as_ushort(__float2bfloat16_rn(hi_e)) << 16)
         |  (uint32_t)__bfloat16_as_ushort(__float2bfloat16_rn(lo_e));
}
__device__ __forceinline__ void splitbf(float2 v, uint32_t& hiw, uint32_t& low) {
    __nv_bfloat16 h0 = __float2bfloat16_rn(v.x);
    __nv_bfloat16 h1 = __float2bfloat16_rn(v.y);
    hiw = ((uint32_t)__bfloat16_as_ushort(h1) << 16)
        |  (uint32_t)__bfloat16_as_ushort(h0);
    low = packbf(v.x - __bfloat162float(h0), v.y - __bfloat162float(h1));
}

// m16n8k16 bf16 mma, fp32 accumulate (sm_80+ PTX)
#define MMA_BF16(c, a0, a1, a2, a3, b0, b1) \
    asm volatile("mma.sync.aligned.m16n8k16.row.col.f32.bf16.bf16.f32 " \
        "{%0,%1,%2,%3}, {%4,%5,%6,%7}, {%8,%9}, {%0,%1,%2,%3};" \
        : "+f"((c)[0]), "+f"((c)[1]), "+f"((c)[2]), "+f"((c)[3]) \
        : "r"(a0), "r"(a1), "r"(a2), "r"(a3), "r"(b0), "r"(b1))

// paired reduction (sm_90+): one instruction per adjacent col pair
#define REDV2(addr, v0, v1) \
    asm volatile("red.global.add.v2.f32 [%0], {%1,%2};" \
        :: "l"(addr), "f"(v0), "f"(v1) : "memory")

__global__ void k_init(const int* __restrict__ z, const float* __restrict__ emb) {
    int i = blockIdx.x * 256 + threadIdx.x;
    if (i < NNODE * HD) {
        g_h[i] = emb[(z[i >> 7] << 7) | (i & 127)];
        g_agg[i] = 0.0f;
    }
}

__global__ void k_d2(const float* __restrict__ pos, const int* __restrict__ ei) {
    int e = blockIdx.x * 256 + threadIdx.x;
    if (e < NEDGE) {
        int r = ei[e], c = ei[NEDGE + e];
        float dx = pos[3 * r + 0] - pos[3 * c + 0];
        float dy = pos[3 * r + 1] - pos[3 * c + 1];
        float dz = pos[3 * r + 2] - pos[3 * c + 2];
        g_d2[e] = dx * dx + dy * dy + dz * dz;
    }
}

// Merged fragment-major split-bf16 weight image builder (all three N=128 images
// in ONE launch so the ncu capture window lands on k_edge).
// Per-layer entry budget: [0,4096) -> g_w2te (ew2, K=128),
// [4096,12288) -> g_nw1te (nw1, K=256), [12288,16384) -> g_nw2te (nw2, K=128).
__global__ void k_prepw_all(const float* __restrict__ ew2,
                            const float* __restrict__ nw1,
                            const float* __restrict__ nw2) {
    int idx = blockIdx.x * 256 + threadIdx.x;
    if (idx >= NLAYER * 16384) return;
    int l = idx / 16384, rr = idx % 16384;
    const float* W;
    uint4* dst;
    int r;
    if (rr < 4096)        { W = ew2 + (size_t)l * HD * HD;     dst = &g_w2te[l][0];  r = rr; }
    else if (rr < 12288)  { W = nw1 + (size_t)l * 2 * HD * HD; dst = &g_nw1te[l][0]; r = rr - 4096; }
    else                  { W = nw2 + (size_t)l * HD * HD;     dst = &g_nw2te[l][0]; r = rr - 12288; }
    int ks = r >> 9, s = (r >> 5) & 15, lane = r & 31;
    int g = lane >> 2, t = lane & 3;
    int n = 8 * s + g;
    int kp0 = 8 * ks + t, kp1 = kp0 + 4;

    uint4 v;
    splitbf(make_float2(W[(size_t)(2 * kp0) * HD + n],
                        W[(size_t)(2 * kp0 + 1) * HD + n]), v.x, v.y);
    splitbf(make_float2(W[(size_t)(2 * kp1) * HD + n],
                        W[(size_t)(2 * kp1 + 1) * HD + n]), v.z, v.w);
    dst[r] = v;
}

// Fragment-major image for edge W1 as fused P||Q GEMM (K=128, N=256).
__global__ void k_prepw1(const float* __restrict__ ew1) {
    int idx = blockIdx.x * 256 + threadIdx.x;     // NLAYER * 8192
    if (idx >= NLAYER * 8192) return;
    int l = idx >> 13, r = idx & 8191;
    int ks = r >> 10, s = (r >> 5) & 31, lane = r & 31;
    int g = lane >> 2, t = lane & 3;
    int n = 8 * s + g;                 // 0..255
    int j = n & 127;
    int koff = (n >= 128) ? 128 : 0;
    int kp0 = 8 * ks + t, kp1 = kp0 + 4;
    const float* W = ew1 + (size_t)l * 257 * HD;

    uint4 v;
    splitbf(make_float2(W[(size_t)(2 * kp0 + koff) * HD + j],
                        W[(size_t)(2 * kp0 + 1 + koff) * HD + j]), v.x, v.y);
    splitbf(make_float2(W[(size_t)(2 * kp1 + koff) * HD + j],
                        W[(size_t)(2 * kp1 + 1 + koff) * HD + j]), v.z, v.w);
    g_w1te[l][r] = v;
}

// P||Q = h @ [W1_top || W1_bot] on tensor cores (Round-14, proven).
__global__ __launch_bounds__(512) void k_pq(int layer) {
    __shared__ uint32_t xhi[TE][68];
    __shared__ uint32_t xlo[TE][68];

    const int tid = threadIdx.x;
    const int warp = tid >> 5, lane = tid & 31;
    const int nb0 = blockIdx.x * TE;

    for (int r = warp; r < TE; r += 16) {
        int node = nb0 + r;
        if (node >= NNODE) node = 0;
        const float* hp = g_h + (size_t)node * HD;
        #pragma unroll
        for (int s = 0; s < 2; s++) {
            int kp = lane + 32 * s;
            float2 hv = __ldg((const float2*)(hp + 2 * kp));
            splitbf(hv, xhi[r][kp], xlo[r][kp]);
        }
    }
    __syncthreads();

    const int g = lane >> 2, t = lane & 3;
    const int m0 = 16 * (warp & 3);
    const int sbase = (warp >> 2) * 8;
    const int n0 = 8 * sbase;
    const int r0 = m0 + g, r1 = m0 + 8 + g;

    float c[8][4];
    #pragma unroll
    for (int s = 0; s < 8; s++)
        #pragma unroll
        for (int q = 0; q < 4; q++) c[s][q] = 0.0f;

    const uint4* bw = &g_w1te[layer][0];

    #pragma unroll
    for (int ks = 0; ks < 8; ks++) {
        uint32_t a0h = xhi[r0][8 * ks + t];
        uint32_t a1h = xhi[r1][8 * ks + t];
        uint32_t a2h = xhi[r0][8 * ks + 4 + t];
        uint32_t a3h = xhi[r1][8 * ks + 4 + t];
        uint32_t a0l = xlo[r0][8 * ks + t];
        uint32_t a1l = xlo[r1][8 * ks + t];
        uint32_t a2l = xlo[r0][8 * ks + 4 + t];
        uint32_t a3l = xlo[r1][8 * ks + 4 + t];
        #pragma unroll
        for (int s = 0; s < 8; s++) {
            uint4 B = __ldg(bw + ((ks * 32 + sbase + s) * 32 + lane));
            MMA_BF16(c[s], a0h, a1h, a2h, a3h, B.x, B.z);
            MMA_BF16(c[s], a0l, a1l, a2l, a3l, B.x, B.z);
            MMA_BF16(c[s], a0h, a1h, a2h, a3h, B.y, B.w);
        }
    }

    {
        int nd0 = nb0 + r0, nd1 = nb0 + r1;
        #pragma unroll
        for (int s = 0; s < 8; s++) {
            int col = n0 + 8 * s + 2 * t;
            float* base = (col < 128) ? g_P : g_Q;
            int cc = col & 127;
            if (nd0 < NNODE)
                *(float2*)(base + (size_t)nd0 * HD + cc) = make_float2(c[s][0], c[s][1]);
            if (nd1 < NNODE)
                *(float2*)(base + (size_t)nd1 * HD + cc) = make_float2(c[s][2], c[s][3]);
        }
    }
}

// Edge kernel: tensor-core GEMM2 (R12/R14 proven shape) with float4 gather
// and paired v2 reductions in the direct (untransposed) epilogue.
__global__ __launch_bounds__(256) void k_edge(
    const int* __restrict__ ei,
    const float* __restrict__ W1,            // row 256 = d2 weights
    const float* __restrict__ b1,
    const float* __restrict__ b2, int layer)
{
    __shared__ uint32_t xhi[TE][68];
    __shared__ uint32_t xlo[TE][68];
    __shared__ int srow[TE], scols[TE];
    __shared__ float sd2[TE], s_b1[HD], s_wl[HD];

    const int tid = threadIdx.x;
    const int warp = tid >> 5, lane = tid & 31;
    const int e0 = blockIdx.x * TE;

    if (tid < TE) { srow[tid] = ei[e0 + tid]; sd2[tid] = g_d2[e0 + tid]; }
    else if (tid < 2 * TE) scols[tid - TE] = ei[NEDGE + e0 + (tid - TE)];
    if (tid < HD) {
        s_b1[tid] = __ldg(b1 + tid);
        s_wl[tid] = __ldg(W1 + 256 * HD + tid);
    }
    __syncthreads();

    // gather + add + silu + split-bf16, one float4 per lane per table
    for (int e = warp; e < TE; e += 8) {
        const float4* pp = (const float4*)(g_P + (size_t)srow[e] * HD);
        const float4* qq = (const float4*)(g_Q + (size_t)scols[e] * HD);
        float d2e = sd2[e];
        float4 pv = __ldg(pp + lane);
        float4 qv = __ldg(qq + lane);
        int k0 = 4 * lane;
        float u0 = silu(pv.x + qv.x + d2e * s_wl[k0 + 0] + s_b1[k0 + 0]);
        float u1 = silu(pv.y + qv.y + d2e * s_wl[k0 + 1] + s_b1[k0 + 1]);
        float u2 = silu(pv.z + qv.z + d2e * s_wl[k0 + 2] + s_b1[k0 + 2]);
        float u3 = silu(pv.w + qv.w + d2e * s_wl[k0 + 3] + s_b1[k0 + 3]);
        splitbf(make_float2(u0, u1), xhi[e][2 * lane],     xlo[e][2 * lane]);
        splitbf(make_float2(u2, u3), xhi[e][2 * lane + 1], xlo[e][2 * lane + 1]);
    }
    __syncthreads();

    const int g = lane >> 2, t = lane & 3;
    const int m0 = 16 * (warp & 3);
    const int sbase = (warp >> 2) * 8;
    const int n0 = 8 * sbase;
    const int r0 = m0 + g, r1 = m0 + 8 + g;

    float c[8][4];
    #pragma unroll
    for (int s = 0; s < 8; s++)
        #pragma unroll
        for (int q = 0; q < 4; q++) c[s][q] = 0.0f;

    const uint4* bw = &g_w2te[layer][0];

    #pragma unroll
    for (int ks = 0; ks < 8; ks++) {
        uint32_t a0h = xhi[r0][8 * ks + t];
        uint32_t a1h = xhi[r1][8 * ks + t];
        uint32_t a2h = xhi[r0][8 * ks + 4 + t];
        uint32_t a3h = xhi[r1][8 * ks + 4 + t];
        uint32_t a0l = xlo[r0][8 * ks + t];
        uint32_t a1l = xlo[r1][8 * ks + t];
        uint32_t a2l = xlo[r0][8 * ks + 4 + t];
        uint32_t a3l = xlo[r1][8 * ks + 4 + t];
        #pragma unroll
        for (int s = 0; s < 8; s++) {
            uint4 B = __ldg(bw + ((ks * 16 + sbase + s) * 32 + lane));
            MMA_BF16(c[s], a0h, a1h, a2h, a3h, B.x, B.z);
            MMA_BF16(c[s], a0l, a1l, a2l, a3l, B.x, B.z);
            MMA_BF16(c[s], a0h, a1h, a2h, a3h, B.y, B.w);
        }
    }

    // epilogue: silu(+b2), paired v2 reductions (addresses 8B-aligned pairs)
    {
        float* ra = g_agg + (size_t)srow[r0] * HD;
        float* rb = g_agg + (size_t)srow[r1] * HD;
        #pragma unroll
        for (int s = 0; s < 8; s++) {
            int col = n0 + 8 * s + 2 * t;
            float bb0 = __ldg(b2 + col), bb1 = __ldg(b2 + col + 1);
            REDV2(ra + col, silu(c[s][0] + bb0), silu(c[s][1] + bb1));
            REDV2(rb + col, silu(c[s][2] + bb0), silu(c[s][3] + bb1));
        }
    }
}

// Node MLP + residual + LayerNorm on tensor cores (Round-13, proven).
__global__ __launch_bounds__(256) void k_node(
    const float* __restrict__ b1, const float* __restrict__ b2,
    const float* __restrict__ lng, const float* __restrict__ lnb,
    float* __restrict__ out, int use_out, int layer)
{
    __shared__ __align__(16) unsigned char sbuf0[64 * 132 * 4];
    __shared__ __align__(16) unsigned char sbuf1[64 * 132 * 4];
    __shared__ float s_b1[HD], s_b2[HD], s_g[HD], s_bb[HD];

    uint32_t (*xhi)[132] = (uint32_t(*)[132])sbuf0;
    uint32_t (*xlo)[132] = (uint32_t(*)[132])sbuf1;
    uint32_t (*thi)[68]  = (uint32_t(*)[68])sbuf0;
    uint32_t (*tlo)[68]  = (uint32_t(*)[68])sbuf1;
    float (*ys)[132]     = (float(*)[132])sbuf0;

    const int tid = threadIdx.x;
    const int warp = tid >> 5, lane = tid & 31;
    const int nb0 = blockIdx.x * TE;

    if (tid < HD) {
        s_b1[tid] = __ldg(b1 + tid);
        s_b2[tid] = __ldg(b2 + tid);
        s_g[tid]  = __ldg(lng + tid);
        s_bb[tid] = __ldg(lnb + tid);
    }

    for (int r = warp; r < TE; r += 8) {
        int node = nb0 + r;
        int valid = node < NNODE;
        if (!valid) node = 0;
        const float* hp = g_h + (size_t)node * HD;
        float* ap = g_agg + (size_t)node * HD;
        #pragma unroll
        for (int s = 0; s < 2; s++) {
            int kp = lane + 32 * s;
            float2 hv = __ldg((const float2*)(hp + 2 * kp));
            splitbf(hv, xhi[r][kp], xlo[r][kp]);
            float2 av = *(const float2*)(ap + 2 * kp);
            splitbf(av, xhi[r][64 + kp], xlo[r][64 + kp]);
            if (valid) *(float2*)(ap + 2 * kp) = make_float2(0.f, 0.f);
        }
    }
    __syncthreads();

    const int g = lane >> 2, t = lane & 3;
    const int m0 = 16 * (warp & 3);
    const int sbase = (warp >> 2) * 8;
    const int n0 = 8 * sbase;
    const int r0 = m0 + g, r1 = m0 + 8 + g;

    float c[8][4];
    #pragma unroll
    for (int s = 0; s < 8; s++)
        #pragma unroll
        for (int q = 0; q < 4; q++) c[s][q] = 0.0f;

    {
        const uint4* bw = &g_nw1te[layer][0];
        #pragma unroll
        for (int ks = 0; ks < 16; ks++) {
            uint32_t a0h = xhi[r0][8 * ks + t];
            uint32_t a1h = xhi[r1][8 * ks + t];
            uint32_t a2h = xhi[r0][8 * ks + 4 + t];
            uint32_t a3h = xhi[r1][8 * ks + 4 + t];
            uint32_t a0l = xlo[r0][8 * ks + t];
            uint32_t a1l = xlo[r1][8 * ks + t];
            uint32_t a2l = xlo[r0][8 * ks + 4 + t];
            uint32_t a3l = xlo[r1][8 * ks + 4 + t];
            #pragma unroll
            for (int s = 0; s < 8; s++) {
                uint4 B = __ldg(bw + ((ks * 16 + sbase + s) * 32 + lane));
                MMA_BF16(c[s], a0h, a1h, a2h, a3h, B.x, B.z);
                MMA_BF16(c[s], a0l, a1l, a2l, a3l, B.x, B.z);
                MMA_BF16(c[s], a0h, a1h, a2h, a3h, B.y, B.w);
            }
        }
    }
    __syncthreads();

    #pragma unroll
    for (int s = 0; s < 8; s++) {
        int col = n0 + 8 * s + 2 * t;
        int kt = (col >> 1);
        float u0 = silu(c[s][0] + s_b1[col]);
        float u1 = silu(c[s][1] + s_b1[col + 1]);
        float u2 = silu(c[s][2] + s_b1[col]);
        float u3 = silu(c[s][3] + s_b1[col + 1]);
        splitbf(make_float2(u0, u1), thi[r0][kt], tlo[r0][kt]);
        splitbf(make_float2(u2, u3), thi[r1][kt], tlo[r1][kt]);
    }
    __syncthreads();

    #pragma unroll
    for (int s = 0; s < 8; s++)
        #pragma unroll
        for (int q = 0; q < 4; q++) c[s][q] = 0.0f;
    {
        const uint4* bw = &g_nw2te[layer][0];
        #pragma unroll
        for (int ks = 0; ks < 8; ks++) {
            uint32_t a0h = thi[r0][8 * ks + t];
            uint32_t a1h = thi[r1][8 * ks + t];
            uint32_t a2h = thi[r0][8 * ks + 4 + t];
            uint32_t a3h = thi[r1][8 * ks + 4 + t];
            uint32_t a0l = tlo[r0][8 * ks + t];
            uint32_t a1l = tlo[r1][8 * ks + t];
            uint32_t a2l = tlo[r0][8 * ks + 4 + t];
            uint32_t a3l = tlo[r1][8 * ks + 4 + t];
            #pragma unroll
            for (int s = 0; s < 8; s++) {
                uint4 B = __ldg(bw + ((ks * 16 + sbase + s) * 32 + lane));
                MMA_BF16(c[s], a0h, a1h, a2h, a3h, B.x, B.z);
                MMA_BF16(c[s], a0l, a1l, a2l, a3l, B.x, B.z);
                MMA_BF16(c[s], a0h, a1h, a2h, a3h, B.y, B.w);
            }
        }
    }
    __syncthreads();

    {
        int nd0 = nb0 + r0; if (nd0 >= NNODE) nd0 = 0;
        int nd1 = nb0 + r1; if (nd1 >= NNODE) nd1 = 0;
        const float* hp0 = g_h + (size_t)nd0 * HD;
        const float* hp1 = g_h + (size_t)nd1 * HD;
        #pragma unroll
        for (int s = 0; s < 8; s++) {
            int col = n0 + 8 * s + 2 * t;
            float2 h0 = __ldg((const float2*)(hp0 + col));
            float2 h1 = __ldg((const float2*)(hp1 + col));
            ys[r0][col]     = c[s][0] + s_b2[col]     + h0.x;
            ys[r0][col + 1] = c[s][1] + s_b2[col + 1] + h0.y;
            ys[r1][col]     = c[s][2] + s_b2[col]     + h1.x;
            ys[r1][col + 1] = c[s][3] + s_b2[col + 1] + h1.y;
        }
    }
    __syncthreads();

    float* hout = use_out ? out : g_h;
    #pragma unroll
    for (int tt = 0; tt < 8; tt++) {
        int e = warp * 8 + tt;
        int node = nb0 + e;
        float v0 = ys[e][lane +  0];
        float v1 = ys[e][lane + 32];
        float v2 = ys[e][lane + 64];
        float v3 = ys[e][lane + 96];
        float s  = v0 + v1 + v2 + v3;
        float ss = fmaf(v0, v0, fmaf(v1, v1, fmaf(v2, v2, v3 * v3)));
        #pragma unroll
        for (int o = 16; o; o >>= 1) {
            s  += __shfl_xor_sync(0xffffffffu, s, o);
            ss += __shfl_xor_sync(0xffffffffu, ss, o);
        }
        float mu  = s * (1.0f / 128.0f);
        float inv = rsqrtf(ss * (1.0f / 128.0f) - mu * mu + 1e-5f);
        if (node < NNODE) {
            float* dst = hout + (size_t)node * HD;
            dst[lane +  0] = fmaf(s_g[lane +  0], (v0 - mu) * inv, s_bb[lane +  0]);
            dst[lane + 32] = fmaf(s_g[lane + 32], (v1 - mu) * inv, s_bb[lane + 32]);
            dst[lane + 64] = fmaf(s_g[lane + 64], (v2 - mu) * inv, s_bb[lane + 64]);
            dst[lane + 96] = fmaf(s_g[lane + 96], (v3 - mu) * inv, s_bb[lane + 96]);
        }
    }
}

extern "C" void kernel_launch(void* const* d_in, const int* in_sizes, int n_in,
                              void* d_out, int out_size) {
    const int*   z   = (const int*)d_in[0];
    const float* pos = (const float*)d_in[1];
    const int*   ei  = (const int*)d_in[2];
    const float* emb = (const float*)d_in[3];
    const float* ew1 = (const float*)d_in[4];
    const float* eb1 = (const float*)d_in[5];
    const float* ew2 = (const float*)d_in[6];
    const float* eb2 = (const float*)d_in[7];
    const float* nw1 = (const float*)d_in[8];
    const float* nb1 = (const float*)d_in[9];
    const float* nw2 = (const float*)d_in[10];
    const float* nb2 = (const float*)d_in[11];
    const float* lng = (const float*)d_in[12];
    const float* lnb = (const float*)d_in[13];
    float* out = (float*)d_out;

    // Launch order matters for ncu (-s 5 -c 1 captures launch #6 = k_edge L0):
    // 1:init 2:d2 3:prepw_all 4:prepw1 5:pq 6:edge ...
    k_init<<<(NNODE * HD + 255) / 256, 256>>>(z, emb);
    k_d2<<<(NEDGE + 255) / 256, 256>>>(pos, ei);
    k_prepw_all<<<(NLAYER * 16384 + 255) / 256, 256>>>(ew2, nw1, nw2);
    k_prepw1<<<(NLAYER * 8192 + 255) / 256, 256>>>(ew1);

    const int pqgrid = (NNODE + TE - 1) / TE;   // 782
    const int egrid  = NEDGE / TE;              // 12500
    const int ngrid  = (NNODE + TE - 1) / TE;   // 782

    for (int l = 0; l < NLAYER; l++) {
        const float* W1l = ew1 + (size_t)l * 257 * HD;
        k_pq<<<pqgrid, 512>>>(l);
        k_edge<<<egrid, 256>>>(ei, W1l, eb1 + l * HD, eb2 + l * HD, l);
        k_node<<<ngrid, 256>>>(nb1 + l * HD, nb2 + l * HD,
                               lng + l * HD, lnb + l * HD,
                               out, (l == NLAYER - 1) ? 1 : 0, l);
    }
}